// round 4
// baseline (speedup 1.0000x reference)
#include <cuda_runtime.h>
#include <cstdint>

// VanillaDynamicRouting: routing logits receive only per-row scalar updates
// (broadcast across all K columns) starting from zero -> logits constant in k
// at every iteration -> every softmax is uniform -> output == 1/K = 1/512
// exactly, independent of x and W. Pure 32 MiB fp32 fill.
//
// R4: discriminating experiment. STG-only (R2) and TMA-only (R3) both
// plateau at ~4.0-4.3 TB/s. If those are separate per-path ports, driving
// both concurrently should add; if it's the shared LTS write port, this is
// neutral and 7.7us is the floor.
//
// Each of 512 CTAs owns 64 KiB: first 32 KiB via 2x 16KiB cp.async.bulk
// (TMA engine), second 32 KiB via 256 threads x 8 STG.128 — concurrent.

#define TILE_BYTES   16384
#define BULK_STORES  2
#define BULK_BYTES   (TILE_BYTES * BULK_STORES)     // 32 KiB
#define STG_BYTES    32768                          // 32 KiB
#define CHUNK_BYTES  (BULK_BYTES + STG_BYTES)       // 64 KiB
#define NCTAS        512
#define NTHREADS     256

__global__ void __launch_bounds__(NTHREADS)
VanillaDynamicRouting_78477642432579_kernel(float* __restrict__ out) {
    __shared__ __align__(1024) float tile[TILE_BYTES / 4];

    const float v = 1.0f / 512.0f;  // exact in fp32
    const float4 val = make_float4(v, v, v, v);

    // Fill the 16 KiB smem tile: 1024 float4 / 256 threads = 4 each.
    float4* t4 = reinterpret_cast<float4*>(tile);
#pragma unroll
    for (int j = 0; j < (TILE_BYTES / 16) / NTHREADS; ++j)
        t4[threadIdx.x + j * NTHREADS] = val;

    asm volatile("fence.proxy.async.shared::cta;" ::: "memory");
    __syncthreads();

    char* chunk = reinterpret_cast<char*>(out) +
                  (size_t)blockIdx.x * CHUNK_BYTES;

    // Launch the async bulk stores first so the TMA engine drains while
    // the threads push STGs on the LSU path.
    if (threadIdx.x == 0) {
        uint32_t saddr;
        asm("{ .reg .u64 t; cvta.to.shared.u64 t, %1; cvt.u32.u64 %0, t; }"
            : "=r"(saddr) : "l"(tile));
#pragma unroll
        for (int s = 0; s < BULK_STORES; ++s) {
            asm volatile(
                "cp.async.bulk.global.shared::cta.bulk_group [%0], [%1], %2;"
                :: "l"(chunk + (size_t)s * TILE_BYTES), "r"(saddr),
                   "r"((int)TILE_BYTES)
                : "memory");
        }
        asm volatile("cp.async.bulk.commit_group;" ::: "memory");
    }

    // STG half: 32 KiB = 2048 float4; 256 threads x 8, coalesced.
    float4* g4 = reinterpret_cast<float4*>(chunk + BULK_BYTES);
#pragma unroll
    for (int j = 0; j < (STG_BYTES / 16) / NTHREADS; ++j)
        g4[threadIdx.x + j * NTHREADS] = val;

    // Don't exit with bulk stores in flight.
    if (threadIdx.x == 0)
        asm volatile("cp.async.bulk.wait_group 0;" ::: "memory");
}

extern "C" void kernel_launch(void* const* d_in, const int* in_sizes, int n_in,
                              void* d_out, int out_size) {
    (void)d_in; (void)in_sizes; (void)n_in; (void)out_size;
    // out_size = 16384*512 floats = 32 MiB = NCTAS * CHUNK_BYTES.
    VanillaDynamicRouting_78477642432579_kernel<<<NCTAS, NTHREADS>>>(
        (float*)d_out);
}

// round 5
// speedup vs baseline: 1.4301x; 1.4301x over previous
#include <cuda_runtime.h>
#include <cstdint>

// VanillaDynamicRouting: routing logits only ever receive per-row SCALAR
// updates (broadcast across all K columns) starting from zero -> logits are
// constant in k at every iteration -> every softmax is uniform -> output is
// exactly 1/K = 1/512 everywhere, independent of x and W. Pure 32 MiB fill.
//
// R5: all prior paths (STG.128 any shape, TMA bulk, hybrid) plateau at
// ~4.3 TB/s with L1TEX the busiest unit in every profile. Hypothesis: the
// SM-side L1tex request rate is the shared ceiling. sm_100+ 256-bit stores
// (st.global.v8.f32) move the same bytes in half the requests.
// 1024 CTAs x 256 threads x 4 x 32B = 32 MiB exact.

#define NCTAS    1024
#define NTHREADS 256

__global__ void __launch_bounds__(NTHREADS)
VanillaDynamicRouting_78477642432579_kernel(float* __restrict__ out) {
    const float v = 1.0f / 512.0f;  // exact in fp32

    // base byte offset of this thread's first 32B chunk
    unsigned tid = blockIdx.x * NTHREADS + threadIdx.x;
    char* p = reinterpret_cast<char*>(out) + (size_t)tid * 32u;
    const size_t stride = (size_t)NCTAS * NTHREADS * 32u;  // 8 MiB

#pragma unroll
    for (int j = 0; j < 4; ++j) {
        asm volatile(
            "st.global.v8.f32 [%0], {%1, %1, %1, %1, %1, %1, %1, %1};"
            :: "l"(p + j * stride), "f"(v)
            : "memory");
    }
}

extern "C" void kernel_launch(void* const* d_in, const int* in_sizes, int n_in,
                              void* d_out, int out_size) {
    (void)d_in; (void)in_sizes; (void)n_in; (void)out_size;
    // out_size = 16384*512 floats = 32 MiB = 1024*256 threads * 4 * 32 B.
    VanillaDynamicRouting_78477642432579_kernel<<<NCTAS, NTHREADS>>>(
        (float*)d_out);
}